// round 7
// baseline (speedup 1.0000x reference)
#include <cuda_runtime.h>

// YOLO loss: grid (5,3,32) = 480 blocks x 256 threads.
// Block handles (b=blockIdx.z, lvl=blockIdx.y, m in [10*blockIdx.x, +10)).
// Phase 1: threads 0..9 load gt (box/label/mask), compute cell idx/valid -> smem.
// Phase 2: threads 0..199 = one cls float4 + focal each; threads 200..209 = GIoU.
// Deterministic partials + last-block-done reduction.

#define NPART 480
#define NTHREADS 256

__device__ float g_box_part[NPART];
__device__ float g_cls_part[NPART];
__device__ int   g_np_part[NPART];
__device__ unsigned int g_done = 0;

__device__ __forceinline__ float warp_sum(float v) {
    #pragma unroll
    for (int o = 16; o > 0; o >>= 1) v += __shfl_down_sync(0xffffffffu, v, o);
    return v;
}

__global__ void __launch_bounds__(NTHREADS) yolo_smem(
    const float* __restrict__ box_preds,   // [32, 8400, 4]
    const float* __restrict__ cls_preds,   // [32, 8400, 80]
    const float* __restrict__ gt_boxes,    // [32, 50, 4]
    const int*   __restrict__ gt_labels,   // [32, 50]
    const void*  __restrict__ gt_mask,     // [32, 50] bool (byte or int32 layout)
    float*       __restrict__ out)
{
    const int tid  = threadIdx.x;
    const int lane = tid & 31;
    const int wrp  = tid >> 5;
    const int lvl  = blockIdx.y;
    const int b    = blockIdx.z;
    const int mb   = blockIdx.x * 10;      // first of 10 gt boxes for this block

    __shared__ int    s_idx[10];
    __shared__ int    s_lab[10];
    __shared__ int    s_val[10];
    __shared__ float4 s_gt[10];

    if (tid < 10) {
        const int  W      = (lvl == 0) ? 80 : (lvl == 1) ? 40 : 20;
        const int  offset = (lvl == 0) ? 0  : (lvl == 1) ? 6400 : 8000;
        const float inv_s = (lvl == 0) ? 0.125f : (lvl == 1) ? 0.0625f : 0.03125f;

        const int gtoff = b * 50 + mb + tid;
        const float4 gb = __ldg((const float4*)(gt_boxes + (size_t)gtoff * 4));
        const int lab = __ldg(gt_labels + gtoff);

        bool mk;
        {
            const int first = *(const int*)gt_mask;   // broadcast dtype probe
            if ((unsigned)first <= 1u)
                mk = ((const int*)gt_mask)[gtoff] != 0;
            else
                mk = ((const unsigned char*)gt_mask)[gtoff] != 0;
        }

        const int gi = (int)floorf((gb.x + gb.z) * 0.5f * inv_s);
        const int gj = (int)floorf((gb.y + gb.w) * 0.5f * inv_s);
        const bool valid = mk && (gi >= 0) && (gj >= 0) && (gi < W) && (gj < W);

        s_idx[tid] = valid ? (offset + gj * W + gi) : 0;
        s_lab[tid] = lab;
        s_val[tid] = valid ? 1 : 0;
        s_gt[tid]  = gb;
    }
    __syncthreads();

    float cls_acc = 0.0f;
    float box_acc = 0.0f;
    bool  pos     = false;

    if (tid < 200) {
        // cls focal: one float4 chunk per thread
        const int ml    = tid / 20;         // 0..9
        const int chunk = tid - ml * 20;    // 0..19
        if (s_val[ml]) {
            const size_t row = (size_t)b * 8400 + s_idx[ml];
            const float4 xv = __ldg((const float4*)(cls_preds + row * 80 + chunk * 4));
            const int lab = s_lab[ml];
            const int c4 = chunk * 4;
            const float xs[4] = {xv.x, xv.y, xv.z, xv.w};
            #pragma unroll
            for (int k = 0; k < 4; k++) {
                const float x = xs[k];
                const float e = __expf(-x);
                const float inv = 1.0f / (1.0f + e);
                const float L = __logf(1.0f + e);        // softplus(-x)
                if (c4 + k == lab) {
                    const float qq = e * inv;            // 1 - sigmoid(x)
                    cls_acc += 0.25f * qq * qq * L;
                } else {
                    const float p = inv;                 // sigmoid(x)
                    cls_acc += 0.75f * p * p * (x + L);  // softplus(x)
                }
            }
        }
    } else if (tid < 210) {
        // GIoU: one gt box per thread
        const int j = tid - 200;
        if (s_val[j]) {
            pos = true;
            const float4 gb = s_gt[j];
            const float x1 = gb.x, y1 = gb.y, x2 = gb.z, y2 = gb.w;
            const size_t row = (size_t)b * 8400 + s_idx[j];
            const float4 pbv = __ldg((const float4*)(box_preds + row * 4));
            const float px1 = pbv.x, py1 = pbv.y, px2 = pbv.z, py2 = pbv.w;
            const float ix1 = fmaxf(px1, x1), iy1 = fmaxf(py1, y1);
            const float ix2 = fminf(px2, x2), iy2 = fminf(py2, y2);
            const float inter = fmaxf(ix2 - ix1, 0.0f) * fmaxf(iy2 - iy1, 0.0f);
            const float a1 = (px2 - px1) * (py2 - py1);
            const float a2 = (x2 - x1) * (y2 - y1);
            const float uni = a1 + a2 - inter;
            const float iou = inter / uni;
            const float ex1 = fminf(px1, x1), ey1 = fminf(py1, y1);
            const float ex2 = fmaxf(px2, x2), ey2 = fmaxf(py2, y2);
            const float encl = (ex2 - ex1) * (ey2 - ey1);
            box_acc = 1.0f - (iou - (encl - uni) / encl);
        }
    }

    // Block reduction: 2 float warp sums + popc(ballot) for np
    __shared__ float w0[8], w1[8];
    __shared__ int   w2[8];
    const float rb = warp_sum(box_acc);
    const float rc = warp_sum(cls_acc);
    const int   rn = __popc(__ballot_sync(0xffffffffu, pos));
    if (lane == 0) { w0[wrp] = rb; w1[wrp] = rc; w2[wrp] = rn; }
    __syncthreads();

    const int blk = (b * 3 + lvl) * 5 + blockIdx.x;   // 0..479
    if (wrp == 0) {
        float vb = (lane < 8) ? w0[lane] : 0.0f;
        float vc = (lane < 8) ? w1[lane] : 0.0f;
        int   vn = (lane < 8) ? w2[lane] : 0;
        vb = warp_sum(vb); vc = warp_sum(vc);
        #pragma unroll
        for (int o = 4; o > 0; o >>= 1) vn += __shfl_down_sync(0xffffffffu, vn, o);
        if (lane == 0) {
            g_box_part[blk] = vb;
            g_cls_part[blk] = vc;
            g_np_part[blk]  = vn;
        }
    }

    // Last-block-done final reduction over 480 partials
    __shared__ bool s_last;
    __threadfence();
    if (tid == 0) {
        unsigned old = atomicAdd(&g_done, 1u);
        s_last = (old == NPART - 1);
    }
    __syncthreads();
    if (s_last) {
        float vb = *((volatile float*)&g_box_part[tid]);
        float vc = *((volatile float*)&g_cls_part[tid]);
        int   vn = *((volatile int*)&g_np_part[tid]);
        if (tid < NPART - NTHREADS) {
            vb += *((volatile float*)&g_box_part[tid + NTHREADS]);
            vc += *((volatile float*)&g_cls_part[tid + NTHREADS]);
            vn += *((volatile int*)&g_np_part[tid + NTHREADS]);
        }
        vb = warp_sum(vb); vc = warp_sum(vc);
        #pragma unroll
        for (int o = 16; o > 0; o >>= 1) vn += __shfl_down_sync(0xffffffffu, vn, o);
        if (lane == 0) { w0[wrp] = vb; w1[wrp] = vc; w2[wrp] = vn; }
        __syncthreads();
        if (tid == 0) {
            float sb = 0.0f, sc = 0.0f; int sn = 0;
            #pragma unroll
            for (int i = 0; i < 8; i++) { sb += w0[i]; sc += w1[i]; sn += w2[i]; }
            const float denom = (float)(sn > 1 ? sn : 1);
            out[0] = (5.0f * sb + sc) / denom;
            g_done = 0;   // reset for next graph replay
        }
    }
}

extern "C" void kernel_launch(void* const* d_in, const int* in_sizes, int n_in,
                              void* d_out, int out_size)
{
    const float* box_preds = (const float*)d_in[0];
    const float* cls_preds = (const float*)d_in[1];
    const float* gt_boxes  = (const float*)d_in[2];
    const int*   gt_labels = (const int*)d_in[3];
    const void*  gt_mask   = d_in[4];
    float* out = (float*)d_out;

    dim3 grid(5, 3, 32);
    yolo_smem<<<grid, NTHREADS>>>(box_preds, cls_preds, gt_boxes, gt_labels, gt_mask, out);
}

// round 8
// speedup vs baseline: 1.0037x; 1.0037x over previous
#include <cuda_runtime.h>

// YOLO loss: grid (5,3,32) = 480 blocks x 256 threads.
// Phase 1: threads 0..9 load gt -> idx/valid/label in smem.
// Phase 2: threads 0..199 one cls float4 + focal; 200..209 GIoU.
// Block partial -> deterministic fixed-point (2^-32) int64 atomicAdd into 3
// global accumulators. Last-done block reads 3 scalars, writes out, resets.

#define NPART 480
#define NTHREADS 256
#define FP_SCALE 4294967296.0   // 2^32

__device__ unsigned long long g_box_acc = 0ull;
__device__ unsigned long long g_cls_acc = 0ull;
__device__ unsigned long long g_np_acc  = 0ull;
__device__ unsigned int g_done = 0;

__device__ __forceinline__ float warp_sum(float v) {
    #pragma unroll
    for (int o = 16; o > 0; o >>= 1) v += __shfl_down_sync(0xffffffffu, v, o);
    return v;
}

__global__ void __launch_bounds__(NTHREADS) yolo_smem(
    const float* __restrict__ box_preds,   // [32, 8400, 4]
    const float* __restrict__ cls_preds,   // [32, 8400, 80]
    const float* __restrict__ gt_boxes,    // [32, 50, 4]
    const int*   __restrict__ gt_labels,   // [32, 50]
    const void*  __restrict__ gt_mask,     // [32, 50] bool (byte or int32 layout)
    float*       __restrict__ out)
{
    const int tid  = threadIdx.x;
    const int lane = tid & 31;
    const int wrp  = tid >> 5;
    const int b    = blockIdx.z;
    const int mb   = blockIdx.x * 10;

    __shared__ int    s_idx[10];
    __shared__ int    s_lab[10];
    __shared__ int    s_val[10];
    __shared__ float4 s_gt[10];

    if (tid < 10) {
        const int lvl = blockIdx.y;
        const int  W      = (lvl == 0) ? 80 : (lvl == 1) ? 40 : 20;
        const int  offset = (lvl == 0) ? 0  : (lvl == 1) ? 6400 : 8000;
        const float inv_s = (lvl == 0) ? 0.125f : (lvl == 1) ? 0.0625f : 0.03125f;

        const int gtoff = b * 50 + mb + tid;
        const float4 gb = __ldg((const float4*)(gt_boxes + (size_t)gtoff * 4));
        const int lab = __ldg(gt_labels + gtoff);

        bool mk;
        {
            const int first = *(const int*)gt_mask;   // broadcast dtype probe
            if ((unsigned)first <= 1u)
                mk = ((const int*)gt_mask)[gtoff] != 0;
            else
                mk = ((const unsigned char*)gt_mask)[gtoff] != 0;
        }

        const int gi = (int)floorf((gb.x + gb.z) * 0.5f * inv_s);
        const int gj = (int)floorf((gb.y + gb.w) * 0.5f * inv_s);
        const bool valid = mk && (gi >= 0) && (gj >= 0) && (gi < W) && (gj < W);

        s_idx[tid] = valid ? (offset + gj * W + gi) : 0;
        s_lab[tid] = lab;
        s_val[tid] = valid ? 1 : 0;
        s_gt[tid]  = gb;
    }
    __syncthreads();

    float cls_acc = 0.0f;
    float box_acc = 0.0f;
    bool  pos     = false;

    if (tid < 200) {
        const int ml    = tid / 20;
        const int chunk = tid - ml * 20;
        if (s_val[ml]) {
            const size_t row = (size_t)b * 8400 + s_idx[ml];
            const float4 xv = __ldg((const float4*)(cls_preds + row * 80 + chunk * 4));
            const int lab = s_lab[ml];
            const int c4 = chunk * 4;
            const float xs[4] = {xv.x, xv.y, xv.z, xv.w};
            #pragma unroll
            for (int k = 0; k < 4; k++) {
                const float x = xs[k];
                const float e = __expf(-x);
                const float inv = 1.0f / (1.0f + e);
                const float L = __logf(1.0f + e);        // softplus(-x)
                if (c4 + k == lab) {
                    const float qq = e * inv;            // 1 - sigmoid(x)
                    cls_acc += 0.25f * qq * qq * L;
                } else {
                    const float p = inv;                 // sigmoid(x)
                    cls_acc += 0.75f * p * p * (x + L);  // softplus(x)
                }
            }
        }
    } else if (tid < 210) {
        const int j = tid - 200;
        if (s_val[j]) {
            pos = true;
            const float4 gb = s_gt[j];
            const float x1 = gb.x, y1 = gb.y, x2 = gb.z, y2 = gb.w;
            const size_t row = (size_t)b * 8400 + s_idx[j];
            const float4 pbv = __ldg((const float4*)(box_preds + row * 4));
            const float px1 = pbv.x, py1 = pbv.y, px2 = pbv.z, py2 = pbv.w;
            const float ix1 = fmaxf(px1, x1), iy1 = fmaxf(py1, y1);
            const float ix2 = fminf(px2, x2), iy2 = fminf(py2, y2);
            const float inter = fmaxf(ix2 - ix1, 0.0f) * fmaxf(iy2 - iy1, 0.0f);
            const float a1 = (px2 - px1) * (py2 - py1);
            const float a2 = (x2 - x1) * (y2 - y1);
            const float uni = a1 + a2 - inter;
            const float iou = inter / uni;
            const float ex1 = fminf(px1, x1), ey1 = fminf(py1, y1);
            const float ex2 = fmaxf(px2, x2), ey2 = fmaxf(py2, y2);
            const float encl = (ex2 - ex1) * (ey2 - ey1);
            box_acc = 1.0f - (iou - (encl - uni) / encl);
        }
    }

    // Block reduction: warp sums -> smem[8] -> warp 0 -> 3 int64 atomics
    __shared__ float w0[8], w1[8];
    __shared__ int   w2[8];
    const float rb = warp_sum(box_acc);
    const float rc = warp_sum(cls_acc);
    const int   rn = __popc(__ballot_sync(0xffffffffu, pos));
    if (lane == 0) { w0[wrp] = rb; w1[wrp] = rc; w2[wrp] = rn; }
    __syncthreads();

    if (tid == 0) {
        float vb = 0.0f, vc = 0.0f; int vn = 0;
        #pragma unroll
        for (int i = 0; i < 8; i++) { vb += w0[i]; vc += w1[i]; vn += w2[i]; }
        // deterministic fixed-point accumulation (integer add is associative)
        const long long qb = __double2ll_rn((double)vb * FP_SCALE);
        const long long qc = __double2ll_rn((double)vc * FP_SCALE);
        atomicAdd(&g_box_acc, (unsigned long long)qb);
        atomicAdd(&g_cls_acc, (unsigned long long)qc);
        atomicAdd(&g_np_acc,  (unsigned long long)vn);
        __threadfence();
        const unsigned old = atomicAdd(&g_done, 1u);
        if (old == NPART - 1) {
            // last block: 3 scalar reads, finalize, reset for next replay
            const double sb = (double)(long long)g_box_acc * (1.0 / FP_SCALE);
            const double sc = (double)(long long)g_cls_acc * (1.0 / FP_SCALE);
            const long long sn = (long long)g_np_acc;
            const double denom = (double)(sn > 1 ? sn : 1);
            out[0] = (float)((5.0 * sb + sc) / denom);
            g_box_acc = 0ull;
            g_cls_acc = 0ull;
            g_np_acc  = 0ull;
            g_done    = 0u;
        }
    }
}

extern "C" void kernel_launch(void* const* d_in, const int* in_sizes, int n_in,
                              void* d_out, int out_size)
{
    const float* box_preds = (const float*)d_in[0];
    const float* cls_preds = (const float*)d_in[1];
    const float* gt_boxes  = (const float*)d_in[2];
    const int*   gt_labels = (const int*)d_in[3];
    const void*  gt_mask   = d_in[4];
    float* out = (float*)d_out;

    dim3 grid(5, 3, 32);
    yolo_smem<<<grid, NTHREADS>>>(box_preds, cls_preds, gt_boxes, gt_labels, gt_mask, out);
}